// round 1
// baseline (speedup 1.0000x reference)
#include <cuda_runtime.h>

#define NVOX     400000
#define K27      27
#define VB       8
#define CHUNK    32
#define NCHUNKS  (NVOX / CHUNK)          // 12500, exact (400000 % 32 == 0)
#define WSTRIDE  36                      // floats per (g,k,co-pair) row; 144B stride -> conflict-free
#define WS_FLOATS (108 * 8 * WSTRIDE)    // 4*27 gk * 8 pairs * 36 = 31104 floats
#define STAGE_FLOATS (16 * 2 * VB * 64)  // 16 warps * double buffer * 8 rows * 64 floats
#define SMEM_BYTES ((WS_FLOATS + STAGE_FLOATS) * 4)   // 189,952 B

__device__ int g_ctr;

#define DO4(Aq, Wa, Wb)                                                     \
    acc0[v] = fmaf(Aq.x, Wa.x, acc0[v]); acc1[v] = fmaf(Aq.x, Wa.y, acc1[v]); \
    acc0[v] = fmaf(Aq.y, Wa.z, acc0[v]); acc1[v] = fmaf(Aq.y, Wa.w, acc1[v]); \
    acc0[v] = fmaf(Aq.z, Wb.x, acc0[v]); acc1[v] = fmaf(Aq.z, Wb.y, acc1[v]); \
    acc0[v] = fmaf(Aq.w, Wb.z, acc0[v]); acc1[v] = fmaf(Aq.w, Wb.w, acc1[v]);

__global__ void __launch_bounds__(512, 1)
subm_conv_kernel(const float* __restrict__ feat,
                 const float* __restrict__ wgt,
                 const float* __restrict__ bias,
                 const int*   __restrict__ nbr,
                 float*       __restrict__ out)
{
    extern __shared__ float smem[];
    float* ws    = smem;               // transposed/interleaved weights
    float* stage = smem + WS_FLOATS;   // per-warp double-buffered gather staging

    const int tid  = threadIdx.x;
    const int lane = tid & 31;
    const int warp = tid >> 5;
    const unsigned FULL = 0xffffffffu;

    // Fill weight smem: src layout [g][k][ci][co] (co fastest, == linear t).
    // dst: [(g*27+k)][co>>1] row of 36 floats, float index 2*ci + (co&1).
    // => float4 j of a row holds {w[2j][co0], w[2j][co1], w[2j+1][co0], w[2j+1][co1]}.
    for (int t = tid; t < 108 * 256; t += 512) {
        int co = t & 15, ci = (t >> 4) & 15, gk = t >> 8;
        ws[(gk * 8 + (co >> 1)) * WSTRIDE + 2 * ci + (co & 1)] = wgt[t];
    }
    __syncthreads();

    const int g = lane >> 3;            // group owned by this lane
    const float b0 = bias[2 * lane];    // lane owns output channels 2*lane, 2*lane+1
    const float b1 = bias[2 * lane + 1];
    float* mybuf = stage + warp * (2 * VB * 64);

    for (;;) {
        int chunk;
        if (lane == 0) chunk = atomicAdd(&g_ctr, 1);
        chunk = __shfl_sync(FULL, chunk, 0);
        if (chunk >= NCHUNKS) break;

        for (int bb = 0; bb < CHUNK / VB; ++bb) {
            const int vb = chunk * CHUNK + bb * VB;

            // Lane l (<27) holds neighbor index for offset l of each batch voxel.
            int myidx[VB];
            unsigned vbits = 0;
#pragma unroll
            for (int v = 0; v < VB; ++v) {
                int ii = -1;
                if (lane < K27) ii = nbr[(long long)(vb + v) * K27 + lane];
                myidx[v] = ii;
                if (ii >= 0) vbits |= 1u << v;
            }
            unsigned km = __ballot_sync(FULL, vbits != 0);  // offsets with any valid voxel

            float acc0[VB], acc1[VB];
#pragma unroll
            for (int v = 0; v < VB; ++v) { acc0[v] = b0; acc1[v] = b1; }

            // ---- software-pipelined loop over non-empty offsets (all warp-uniform) ----
            float2 R[VB];
            int kcur = __ffs(km) - 1;
            km &= km - 1;
            unsigned bcur = __shfl_sync(FULL, vbits, kcur);
#pragma unroll
            for (int v = 0; v < VB; ++v)
                if (bcur & (1u << v)) {
                    int idx = __shfl_sync(FULL, myidx[v], kcur);
                    R[v] = *(const float2*)(feat + (long long)idx * 64 + 2 * lane);
                }

            int pb = 0;
            while (kcur >= 0) {
                int knxt = -1;
                unsigned bnxt = 0;
                if (km) {
                    knxt = __ffs(km) - 1;
                    km &= km - 1;
                    bnxt = __shfl_sync(FULL, vbits, knxt);
                }

                // Commit current gathered rows to staging buffer pb.
                float* buf = mybuf + pb * (VB * 64);
#pragma unroll
                for (int v = 0; v < VB; ++v)
                    if (bcur & (1u << v))
                        *(float2*)(buf + v * 64 + 2 * lane) = R[v];

                // Prefetch next offset's rows into registers (hides L2 latency).
                if (knxt >= 0) {
#pragma unroll
                    for (int v = 0; v < VB; ++v)
                        if (bnxt & (1u << v)) {
                            int idx = __shfl_sync(FULL, myidx[v], knxt);
                            R[v] = *(const float2*)(feat + (long long)idx * 64 + 2 * lane);
                        }
                }
                __syncwarp();

                // Weights for (g, kcur, co-pair = lane&7): 8 LDS.128, conflict-optimal.
                const float4* wp =
                    (const float4*)(ws + ((g * K27 + kcur) * 8 + (lane & 7)) * WSTRIDE);
                float4 W[8];
#pragma unroll
                for (int j = 0; j < 8; ++j) W[j] = wp[j];

#pragma unroll
                for (int v = 0; v < VB; ++v)
                    if (bcur & (1u << v)) {
                        const float4* a4 = (const float4*)(buf + v * 64 + g * 16);
                        float4 A0 = a4[0], A1 = a4[1], A2 = a4[2], A3 = a4[3];
                        DO4(A0, W[0], W[1]);
                        DO4(A1, W[2], W[3]);
                        DO4(A2, W[4], W[5]);
                        DO4(A3, W[6], W[7]);
                    }

                pb ^= 1;
                kcur = knxt;
                bcur = bnxt;
            }

            // Epilogue: contiguous 256B float2 stores per voxel row.
#pragma unroll
            for (int v = 0; v < VB; ++v)
                *(float2*)(out + (long long)(vb + v) * 64 + 2 * lane) =
                    make_float2(acc0[v], acc1[v]);
        }
    }
}

extern "C" void kernel_launch(void* const* d_in, const int* in_sizes, int n_in,
                              void* d_out, int out_size) {
    const float* feat = (const float*)d_in[0];
    const float* wgt  = (const float*)d_in[1];
    const float* bias = (const float*)d_in[2];
    const int*   nbr  = (const int*)d_in[3];
    float* out = (float*)d_out;

    void* ctr = nullptr;
    cudaGetSymbolAddress(&ctr, g_ctr);
    cudaMemsetAsync(ctr, 0, sizeof(int));

    cudaFuncSetAttribute(subm_conv_kernel,
                         cudaFuncAttributeMaxDynamicSharedMemorySize, SMEM_BYTES);
    subm_conv_kernel<<<160, 512, SMEM_BYTES>>>(feat, wgt, bias, nbr, out);
}